// round 3
// baseline (speedup 1.0000x reference)
#include <cuda_runtime.h>
#include <math.h>

// B=2, L=S=2048, H=8, E=D=32 (fixed by the problem)
namespace {
constexpr int B_ = 2, L_ = 2048, S_ = 2048, H_ = 8, E_ = 32, D_ = 32;
constexpr int BM = 32, BN = 64;
constexpr int NT = 128;
constexpr float INV = 0.17677669529663687f;       // 2^-2.5 = 1/sqrt(32)
constexpr float QS  = 0.07432544468767006f;       // INV^1.5 (folds softmax scale into q,k)
constexpr float KG2 = 2.0f * INV;                 // kg pre-scaled by 2*INV -> pair.hi = 2*cr
constexpr float NEG_MASK = -4294967295.0f * 0.17677669529663687f;
constexpr int PQ = 2 * BM;          // 64 floats per e-row of interleaved (q,qg) pairs
constexpr int PK = 2 * BN;          // 128 floats per e-row of interleaved (k,kg) pairs
constexpr int PP = BN + 4;          // 68: P pitch, conflict-free PV row reads
constexpr int SM_Q = E_ * PQ;       // 2048 floats
constexpr int SM_K = E_ * PK;       // 4096
constexpr int SM_V = BN * D_;       // 2048
constexpr int SM_P = BM * PP;       // 2176
constexpr int SMEM_FLOATS = SM_Q + SM_K + SM_V + SM_P + BM + BN + 3 * BM;
constexpr int SMEM_BYTES = SMEM_FLOATS * 4;       // ~41.5 KB -> 4+ CTAs/SM
}

// ---- packed f32x2 helpers (sm_103a FFMA2 path; PTX-only per SASS quickref) ----
__device__ __forceinline__ unsigned long long pk2(float lo, float hi) {
    unsigned long long r;
    asm("mov.b64 %0, {%1, %2};" : "=l"(r) : "f"(lo), "f"(hi));
    return r;
}
__device__ __forceinline__ float2 upk2(unsigned long long v) {
    float2 r;
    asm("mov.b64 {%0, %1}, %2;" : "=f"(r.x), "=f"(r.y) : "l"(v));
    return r;
}
__device__ __forceinline__ void fma2(unsigned long long& d, unsigned long long a, unsigned long long b) {
    asm("fma.rn.f32x2 %0, %1, %2, %0;" : "+l"(d) : "l"(a), "l"(b));
}
__device__ __forceinline__ void mul2(unsigned long long& d, unsigned long long a, unsigned long long b) {
    asm("mul.rn.f32x2 %0, %1, %2;" : "=l"(d) : "l"(a), "l"(b));
}

__global__ __launch_bounds__(NT, 4)
void gauss_attn(const float* __restrict__ Q, const float* __restrict__ K,
                const float* __restrict__ V, float* __restrict__ O)
{
    extern __shared__ float sm[];
    float* sQi  = sm;                // [E][PQ]  interleaved (q*QS, qg*INV) pairs, row-fastest
    float* sKi  = sQi + SM_Q;        // [E][PK]  interleaved (k*QS, kg*2INV) pairs
    float* sV   = sKi + SM_K;        // [BN][D]
    float* sP   = sV  + SM_V;        // [BM][PP]
    float* sQn  = sP  + SM_P;        // [BM]
    float* sKn  = sQn + BM;          // [BN]
    float* sM   = sKn + BN;          // [BM]
    float* sSum = sM  + BM;          // [BM]
    float* sAl  = sSum + BM;         // [BM]

    const int b  = blockIdx.y / H_;
    const int h  = blockIdx.y % H_;
    const int l0 = (int)(gridDim.x - 1 - blockIdx.x) * BM;   // heavy tiles first

    const int tid = threadIdx.x;
    const int tx  = tid & 15;
    const int ty  = tid >> 4;

    // q[b,l,h,e] flat: ((b*L+l)*H+h)*E+e ; gaussian view row l: (b*L*H + h*L + l)*E + e
    const float* Qb  = Q + ((size_t)(b * L_ + l0) * H_ + h) * E_;
    const float* Qgb = Q + ((size_t)b * L_ * H_ + (size_t)h * L_ + l0) * E_;

    // ---- fill Q pairs (row index fastest across lanes -> 2-wf STS.64) ----
    #pragma unroll
    for (int it = 0; it < 2; it++) {
        int idx = tid + it * NT;
        int r = idx & 31, eg = idx >> 5;              // eg in 0..7
        float4 a = *reinterpret_cast<const float4*>(Qb  + (size_t)r * H_ * E_ + eg * 4);
        float4 g = *reinterpret_cast<const float4*>(Qgb + r * E_ + eg * 4);
        float* base = sQi + 2 * r;
        *reinterpret_cast<float2*>(base + (eg * 4 + 0) * PQ) = make_float2(a.x * QS, g.x * INV);
        *reinterpret_cast<float2*>(base + (eg * 4 + 1) * PQ) = make_float2(a.y * QS, g.y * INV);
        *reinterpret_cast<float2*>(base + (eg * 4 + 2) * PQ) = make_float2(a.z * QS, g.z * INV);
        *reinterpret_cast<float2*>(base + (eg * 4 + 3) * PQ) = make_float2(a.w * QS, g.w * INV);
    }
    if (tid < BM) {
        const float* row = Qgb + tid * E_;
        float s = 0.f;
        #pragma unroll
        for (int e = 0; e < E_; e++) { float v = row[e] * INV; s = fmaf(v, v, s); }
        sQn[tid]  = s;
        sM[tid]   = -INFINITY;
        sSum[tid] = 0.f;
    }

    unsigned long long pacc[4] = {0ull, 0ull, 0ull, 0ull};  // (d0+0,1)(2,3)(4,5)(6,7)
    const int r_pv = tid >> 2;
    const int d0   = (tid & 3) * 8;

    const int ntiles = l0 / BN + 1;
    for (int t = 0; t < ntiles; t++) {
        const int s0 = t * BN;
        __syncthreads();   // prior PV readers done before overwriting K/V

        const float* Kb  = K + ((size_t)(b * S_ + s0) * H_ + h) * E_;
        const float* Kgb = K + ((size_t)b * S_ * H_ + (size_t)h * S_ + s0) * E_;
        const float* Vb  = V + ((size_t)(b * S_ + s0) * H_ + h) * D_;

        #pragma unroll
        for (int it = 0; it < 4; it++) {
            int idx = tid + it * NT;
            int r = idx & 63, eg = idx >> 6;          // eg in 0..7
            float4 a = *reinterpret_cast<const float4*>(Kb  + (size_t)r * H_ * E_ + eg * 4);
            float4 g = *reinterpret_cast<const float4*>(Kgb + r * E_ + eg * 4);
            float* base = sKi + 2 * r;
            *reinterpret_cast<float2*>(base + (eg * 4 + 0) * PK) = make_float2(a.x * QS, g.x * KG2);
            *reinterpret_cast<float2*>(base + (eg * 4 + 1) * PK) = make_float2(a.y * QS, g.y * KG2);
            *reinterpret_cast<float2*>(base + (eg * 4 + 2) * PK) = make_float2(a.z * QS, g.z * KG2);
            *reinterpret_cast<float2*>(base + (eg * 4 + 3) * PK) = make_float2(a.w * QS, g.w * KG2);
        }
        #pragma unroll
        for (int it = 0; it < 4; it++) {
            int idx = tid + it * NT;
            int r = idx >> 3, c = (idx & 7) * 4;
            *reinterpret_cast<float4*>(sV + r * D_ + c) =
                *reinterpret_cast<const float4*>(Vb + (size_t)r * H_ * D_ + c);
        }
        if (tid < BN) {
            const float* row = Kgb + tid * E_;
            float s = 0.f;
            #pragma unroll
            for (int e = 0; e < E_; e++) { float v = row[e] * INV; s = fmaf(v, v, s); }
            sKn[tid] = s;
        }
        __syncthreads();

        // ---- scores: 4x4 pairs per thread, one FFMA2 advances (qk, 2*qg.kg) ----
        unsigned long long acc[16];
        #pragma unroll
        for (int i = 0; i < 16; i++) acc[i] = 0ull;

        #pragma unroll
        for (int e = 0; e < E_; e++) {
            const ulonglong2* qr = reinterpret_cast<const ulonglong2*>(sQi + e * PQ);
            const ulonglong2* kr = reinterpret_cast<const ulonglong2*>(sKi + e * PK);
            ulonglong2 qA = qr[ty], qB = qr[8 + ty];       // rows 2ty,2ty+1 / 16+2ty,17+2ty
            ulonglong2 kA = kr[tx], kB = kr[16 + tx];      // cols 2tx,2tx+1 / 32+2tx,33+2tx
            unsigned long long qp[4] = {qA.x, qA.y, qB.x, qB.y};
            unsigned long long kp[4] = {kA.x, kA.y, kB.x, kB.y};
            #pragma unroll
            for (int i = 0; i < 4; i++)
                #pragma unroll
                for (int j = 0; j < 4; j++)
                    fma2(acc[i * 4 + j], qp[i], kp[j]);
        }

        const int rows[4] = {2 * ty, 2 * ty + 1, 16 + 2 * ty, 17 + 2 * ty};
        const int cols[4] = {2 * tx, 2 * tx + 1, 32 + 2 * tx, 33 + 2 * tx};
        float qn[4], kn[4];
        #pragma unroll
        for (int i = 0; i < 4; i++) qn[i] = sQn[rows[i]];
        #pragma unroll
        for (int j = 0; j < 4; j++) kn[j] = sKn[cols[j]];

        #pragma unroll
        for (int i = 0; i < 4; i++) {
            const int li = l0 + rows[i];
            float z[4];
            #pragma unroll
            for (int j = 0; j < 4; j++) {
                float2 dc = upk2(acc[i * 4 + j]);          // .x = z_pre, .y = 2*cr
                float sq = fmaxf(qn[i] + kn[j] - dc.y, 0.f);
                float zz = dc.x * __expf(-sq);
                z[j] = (s0 + cols[j] > li) ? NEG_MASK : zz;
            }
            float m = fmaxf(fmaxf(z[0], z[1]), fmaxf(z[2], z[3]));
            m = fmaxf(m, __shfl_xor_sync(0xffffffffu, m, 1));
            m = fmaxf(m, __shfl_xor_sync(0xffffffffu, m, 2));
            m = fmaxf(m, __shfl_xor_sync(0xffffffffu, m, 4));
            m = fmaxf(m, __shfl_xor_sync(0xffffffffu, m, 8));
            const float mold = sM[rows[i]];
            const float mn   = fmaxf(mold, m);
            float p0 = __expf(z[0] - mn), p1 = __expf(z[1] - mn);
            float p2 = __expf(z[2] - mn), p3 = __expf(z[3] - mn);
            *reinterpret_cast<float2*>(sP + rows[i] * PP + 2 * tx)      = make_float2(p0, p1);
            *reinterpret_cast<float2*>(sP + rows[i] * PP + 32 + 2 * tx) = make_float2(p2, p3);
            float rs = (p0 + p1) + (p2 + p3);
            rs += __shfl_xor_sync(0xffffffffu, rs, 1);
            rs += __shfl_xor_sync(0xffffffffu, rs, 2);
            rs += __shfl_xor_sync(0xffffffffu, rs, 4);
            rs += __shfl_xor_sync(0xffffffffu, rs, 8);
            if (tx == 0) {
                const float al = __expf(mold - mn);        // 0 on first tile
                sAl[rows[i]]  = al;
                sM[rows[i]]   = mn;
                sSum[rows[i]] = sSum[rows[i]] * al + rs;
            }
        }
        __syncthreads();

        // ---- O = O*alpha + P*V (packed d-pairs) ----
        const float alf = sAl[r_pv];
        const unsigned long long alp = pk2(alf, alf);
        mul2(pacc[0], pacc[0], alp);
        mul2(pacc[1], pacc[1], alp);
        mul2(pacc[2], pacc[2], alp);
        mul2(pacc[3], pacc[3], alp);

        const float* prow = sP + r_pv * PP;
        #pragma unroll
        for (int s4 = 0; s4 < BN; s4 += 4) {
            float4 p = *reinterpret_cast<const float4*>(prow + s4);
            float pv4[4] = {p.x, p.y, p.z, p.w};
            #pragma unroll
            for (int k = 0; k < 4; k++) {
                const float* vr = sV + (s4 + k) * D_ + d0;
                ulonglong2 va = *reinterpret_cast<const ulonglong2*>(vr);
                ulonglong2 vb = *reinterpret_cast<const ulonglong2*>(vr + 4);
                unsigned long long pp = pk2(pv4[k], pv4[k]);
                fma2(pacc[0], pp, va.x);
                fma2(pacc[1], pp, va.y);
                fma2(pacc[2], pp, vb.x);
                fma2(pacc[3], pp, vb.y);
            }
        }
    }

    // ---- finalize ----
    const float isum = 1.f / sSum[r_pv];
    float2 o0 = upk2(pacc[0]), o1 = upk2(pacc[1]), o2 = upk2(pacc[2]), o3 = upk2(pacc[3]);
    float4 w0, w1;
    w0.x = o0.x * isum; w0.y = o0.y * isum; w0.z = o1.x * isum; w0.w = o1.y * isum;
    w1.x = o2.x * isum; w1.y = o2.y * isum; w1.z = o3.x * isum; w1.w = o3.y * isum;
    float* Ob = O + ((size_t)(b * L_ + l0 + r_pv) * H_ + h) * D_ + d0;
    *reinterpret_cast<float4*>(Ob)     = w0;
    *reinterpret_cast<float4*>(Ob + 4) = w1;
}

extern "C" void kernel_launch(void* const* d_in, const int* in_sizes, int n_in,
                              void* d_out, int out_size) {
    const float* Q = (const float*)d_in[0];
    const float* K = (const float*)d_in[1];
    const float* V = (const float*)d_in[2];
    float* O = (float*)d_out;

    cudaFuncSetAttribute(gauss_attn, cudaFuncAttributeMaxDynamicSharedMemorySize, SMEM_BYTES);

    dim3 grid(L_ / BM, B_ * H_);
    gauss_attn<<<grid, NT, SMEM_BYTES>>>(Q, K, V, O);
}

// round 4
// speedup vs baseline: 1.4537x; 1.4537x over previous
#include <cuda_runtime.h>
#include <math.h>

// B=2, L=S=2048, H=8, E=D=32 (fixed by the problem)
namespace {
constexpr int B_ = 2, L_ = 2048, S_ = 2048, H_ = 8, E_ = 32, D_ = 32;
constexpr int BM = 64, BN = 64, PT = 68;
constexpr int NT = 256;
constexpr float INV = 0.17677669529663687f;                       // 1/sqrt(32)
constexpr float NEG_MASK = -4294967295.0f * 0.17677669529663687f; // scale*(-(2^32-1))
constexpr int SMEM_FLOATS = 4 * E_ * PT + BN * D_ + BM * PT + 2 * BM;
constexpr int SMEM_BYTES = SMEM_FLOATS * 4;   // ~61 KB -> 2 CTAs/SM
}

__global__ __launch_bounds__(NT, 2)
void gauss_attn(const float* __restrict__ Q, const float* __restrict__ K,
                const float* __restrict__ V, float* __restrict__ O)
{
    extern __shared__ float sm[];
    float* sQt  = sm;                 // [E][PT] transposed, scaled by INV
    float* sQgt = sQt  + E_ * PT;     // [E][PT]
    float* sKt  = sQgt + E_ * PT;     // [E][PT]
    float* sKgt = sKt  + E_ * PT;     // [E][PT]
    float* sV   = sKgt + E_ * PT;     // [BN][D]
    float* sP   = sV   + BN * D_;     // [BM][PT]  (warp-private rows!)
    float* sQn  = sP   + BM * PT;     // [BM]
    float* sKn  = sQn  + BM;          // [BN]

    const int b  = blockIdx.y / H_;
    const int h  = blockIdx.y % H_;
    const int l0 = (int)(gridDim.x - 1 - blockIdx.x) * BM;   // heavy tiles first

    const int tid = threadIdx.x;
    const int tx  = tid & 15;   // 4 cols each
    const int ty  = tid >> 4;   // 4 rows each

    // q[b,l,h,e] flat: ((b*L+l)*H+h)*E+e ; gaussian view row l: (b*L*H + h*L + l)*E+e
    const float* Qb  = Q + ((size_t)(b * L_ + l0) * H_ + h) * E_;
    const float* Qgb = Q + ((size_t)b * L_ * H_ + (size_t)h * L_ + l0) * E_;

    #pragma unroll
    for (int it = 0; it < 2; it++) {
        int idx = tid + it * NT;
        int r = idx >> 3, c = (idx & 7) * 4;
        float4 a = *reinterpret_cast<const float4*>(Qb  + (size_t)r * H_ * E_ + c);
        float4 g = *reinterpret_cast<const float4*>(Qgb + r * E_ + c);
        sQt [(c + 0) * PT + r] = a.x * INV; sQt [(c + 1) * PT + r] = a.y * INV;
        sQt [(c + 2) * PT + r] = a.z * INV; sQt [(c + 3) * PT + r] = a.w * INV;
        sQgt[(c + 0) * PT + r] = g.x * INV; sQgt[(c + 1) * PT + r] = g.y * INV;
        sQgt[(c + 2) * PT + r] = g.z * INV; sQgt[(c + 3) * PT + r] = g.w * INV;
    }
    if (tid < BM) {
        const float* row = Qgb + tid * E_;
        float s = 0.f;
        #pragma unroll
        for (int e = 0; e < E_; e++) { float v = row[e] * INV; s = fmaf(v, v, s); }
        sQn[tid] = s;
    }

    float acc[8];
    #pragma unroll
    for (int i = 0; i < 8; i++) acc[i] = 0.f;
    float rsum = 0.f;                       // row softmax denominator (m = 0)

    const int r_pv = tid >> 2;
    const int d0   = (tid & 3) * 8;

    const int ntiles = l0 / BN + 1;

    // ---- prefetch tile 0 into registers ----
    float4 stK[2], stKg[2], stV[2];
    {
        const float* Kb  = K + ((size_t)(b * S_) * H_ + h) * E_;
        const float* Kgb = K + ((size_t)b * S_ * H_ + (size_t)h * S_) * E_;
        const float* Vb  = V + ((size_t)(b * S_) * H_ + h) * D_;
        #pragma unroll
        for (int it = 0; it < 2; it++) {
            int idx = tid + it * NT;
            int r = idx >> 3, c = (idx & 7) * 4;
            stK [it] = *reinterpret_cast<const float4*>(Kb  + (size_t)r * H_ * E_ + c);
            stKg[it] = *reinterpret_cast<const float4*>(Kgb + r * E_ + c);
            stV [it] = *reinterpret_cast<const float4*>(Vb  + (size_t)r * H_ * D_ + c);
        }
    }

    for (int t = 0; t < ntiles; t++) {
        const int s0 = t * BN;
        __syncthreads();   // prior tile's PV readers done with sV

        // ---- commit staged K/Kg/V to smem ----
        #pragma unroll
        for (int it = 0; it < 2; it++) {
            int idx = tid + it * NT;
            int r = idx >> 3, c = (idx & 7) * 4;
            sKt [(c + 0) * PT + r] = stK[it].x * INV; sKt [(c + 1) * PT + r] = stK[it].y * INV;
            sKt [(c + 2) * PT + r] = stK[it].z * INV; sKt [(c + 3) * PT + r] = stK[it].w * INV;
            sKgt[(c + 0) * PT + r] = stKg[it].x * INV; sKgt[(c + 1) * PT + r] = stKg[it].y * INV;
            sKgt[(c + 2) * PT + r] = stKg[it].z * INV; sKgt[(c + 3) * PT + r] = stKg[it].w * INV;
            *reinterpret_cast<float4*>(sV + r * D_ + c) = stV[it];
        }
        if (tid < BN) {   // |kg|^2 (rows are L1-hot from the staging LDGs)
            const float* row = K + ((size_t)b * S_ * H_ + (size_t)h * S_ + (s0 + tid)) * E_;
            float s = 0.f;
            #pragma unroll
            for (int e8 = 0; e8 < E_; e8 += 4) {
                float4 g = *reinterpret_cast<const float4*>(row + e8);
                s = fmaf(g.x * INV, g.x * INV, s); s = fmaf(g.y * INV, g.y * INV, s);
                s = fmaf(g.z * INV, g.z * INV, s); s = fmaf(g.w * INV, g.w * INV, s);
            }
            sKn[tid] = s;
        }
        __syncthreads();

        // ---- prefetch next tile while computing this one ----
        if (t + 1 < ntiles) {
            const int sn = s0 + BN;
            const float* Kb  = K + ((size_t)(b * S_ + sn) * H_ + h) * E_;
            const float* Kgb = K + ((size_t)b * S_ * H_ + (size_t)h * S_ + sn) * E_;
            const float* Vb  = V + ((size_t)(b * S_ + sn) * H_ + h) * D_;
            #pragma unroll
            for (int it = 0; it < 2; it++) {
                int idx = tid + it * NT;
                int r = idx >> 3, c = (idx & 7) * 4;
                stK [it] = *reinterpret_cast<const float4*>(Kb  + (size_t)r * H_ * E_ + c);
                stKg[it] = *reinterpret_cast<const float4*>(Kgb + r * E_ + c);
                stV [it] = *reinterpret_cast<const float4*>(Vb  + (size_t)r * H_ * D_ + c);
            }
        }

        // ---- 64x64 scores: 4x4 micro-tile, two dot products ----
        float dt[16], cr[16];
        #pragma unroll
        for (int i = 0; i < 16; i++) { dt[i] = 0.f; cr[i] = 0.f; }

        #pragma unroll
        for (int e = 0; e < E_; e++) {
            const float4 qa = *reinterpret_cast<const float4*>(sQt  + e * PT + ty * 4);
            const float4 ka = *reinterpret_cast<const float4*>(sKt  + e * PT + tx * 4);
            const float4 qg = *reinterpret_cast<const float4*>(sQgt + e * PT + ty * 4);
            const float4 kg = *reinterpret_cast<const float4*>(sKgt + e * PT + tx * 4);
            const float qv[4] = {qa.x, qa.y, qa.z, qa.w};
            const float kv[4] = {ka.x, ka.y, ka.z, ka.w};
            const float gv[4] = {qg.x, qg.y, qg.z, qg.w};
            const float jv[4] = {kg.x, kg.y, kg.z, kg.w};
            #pragma unroll
            for (int i = 0; i < 4; i++)
                #pragma unroll
                for (int j = 0; j < 4; j++) {
                    dt[i * 4 + j] = fmaf(qv[i], kv[j], dt[i * 4 + j]);
                    cr[i * 4 + j] = fmaf(gv[i], jv[j], cr[i * 4 + j]);
                }
        }

        float qn[4], kn[4];
        #pragma unroll
        for (int i = 0; i < 4; i++) qn[i] = sQn[ty * 4 + i];
        #pragma unroll
        for (int j = 0; j < 4; j++) kn[j] = sKn[tx * 4 + j];

        // p = exp(scale * qk * exp(-sqdist))  — fixed m=0, no reductions at all
        if (t == ntiles - 1) {   // only the diagonal tile needs masking
            #pragma unroll
            for (int i = 0; i < 4; i++) {
                const int li = l0 + ty * 4 + i;
                float4 p;
                float z[4];
                #pragma unroll
                for (int j = 0; j < 4; j++) {
                    float sq = fmaxf(qn[i] + kn[j] - 2.f * cr[i * 4 + j], 0.f);
                    float zz = INV * dt[i * 4 + j] * __expf(-sq);
                    z[j] = (s0 + tx * 4 + j > li) ? NEG_MASK : zz;
                }
                p.x = __expf(z[0]); p.y = __expf(z[1]);
                p.z = __expf(z[2]); p.w = __expf(z[3]);
                *reinterpret_cast<float4*>(sP + (ty * 4 + i) * PT + tx * 4) = p;
            }
        } else {
            #pragma unroll
            for (int i = 0; i < 4; i++) {
                float4 p;
                #pragma unroll
                for (int j = 0; j < 4; j++) {
                    float sq = fmaxf(qn[i] + kn[j] - 2.f * cr[i * 4 + j], 0.f);
                    float zz = INV * dt[i * 4 + j] * __expf(-sq);
                    (&p.x)[j] = __expf(zz);
                }
                *reinterpret_cast<float4*>(sP + (ty * 4 + i) * PT + tx * 4) = p;
            }
        }

        // P rows 8w..8w+7 are written and read by warp w only
        __syncwarp();

        // ---- O += P*V ; row sum for free (every thread scans its full P row) ----
        const float* prow = sP + r_pv * PT;
        #pragma unroll
        for (int s4 = 0; s4 < BN; s4 += 4) {
            float4 p = *reinterpret_cast<const float4*>(prow + s4);
            rsum += (p.x + p.y) + (p.z + p.w);
            const float pv4[4] = {p.x, p.y, p.z, p.w};
            #pragma unroll
            for (int k = 0; k < 4; k++) {
                const float4 va = *reinterpret_cast<const float4*>(sV + (s4 + k) * D_ + d0);
                const float4 vb = *reinterpret_cast<const float4*>(sV + (s4 + k) * D_ + d0 + 4);
                acc[0] = fmaf(pv4[k], va.x, acc[0]);
                acc[1] = fmaf(pv4[k], va.y, acc[1]);
                acc[2] = fmaf(pv4[k], va.z, acc[2]);
                acc[3] = fmaf(pv4[k], va.w, acc[3]);
                acc[4] = fmaf(pv4[k], vb.x, acc[4]);
                acc[5] = fmaf(pv4[k], vb.y, acc[5]);
                acc[6] = fmaf(pv4[k], vb.z, acc[6]);
                acc[7] = fmaf(pv4[k], vb.w, acc[7]);
            }
        }
    }

    // ---- finalize ----
    const float isum = 1.f / rsum;
    float4 o0, o1;
    o0.x = acc[0] * isum; o0.y = acc[1] * isum; o0.z = acc[2] * isum; o0.w = acc[3] * isum;
    o1.x = acc[4] * isum; o1.y = acc[5] * isum; o1.z = acc[6] * isum; o1.w = acc[7] * isum;
    float* Ob = O + ((size_t)(b * L_ + l0 + r_pv) * H_ + h) * D_ + d0;
    *reinterpret_cast<float4*>(Ob)     = o0;
    *reinterpret_cast<float4*>(Ob + 4) = o1;
}

extern "C" void kernel_launch(void* const* d_in, const int* in_sizes, int n_in,
                              void* d_out, int out_size) {
    const float* Q = (const float*)d_in[0];
    const float* K = (const float*)d_in[1];
    const float* V = (const float*)d_in[2];
    float* O = (float*)d_out;

    cudaFuncSetAttribute(gauss_attn, cudaFuncAttributeMaxDynamicSharedMemorySize, SMEM_BYTES);

    dim3 grid(L_ / BM, B_ * H_);
    gauss_attn<<<grid, NT, SMEM_BYTES>>>(Q, K, V, O);
}